// round 1
// baseline (speedup 1.0000x reference)
#include <cuda_runtime.h>
#include <cstdint>

// Problem constants
#define NTOK   (16 * 8192)     // 131072 tokens
#define DM     256
#define DK     64
#define DV     64
#define NQ     256
#define OUT_ELE (16 * 256 * 256)   // 'out' tensor elements; hardattn follows

// Scratch: pooled[b, qslot, v] accumulator (16*256*64 floats)
__device__ float g_pooled[16 * 256 * 64];

// ---------------------------------------------------------------------------
// K0: zero the pooled accumulator (262144 floats = 65536 float4)
// ---------------------------------------------------------------------------
__global__ void __launch_bounds__(256) k_zero() {
    int i = blockIdx.x * 256 + threadIdx.x;
    reinterpret_cast<float4*>(g_pooled)[i] = make_float4(0.f, 0.f, 0.f, 0.f);
}

// ---------------------------------------------------------------------------
// K1: fused  k/v projection -> attn -> argmax -> one-hot write -> scatter-add v
//
// Block = 256 threads (8 warps), grid = 512 blocks, 256 tokens per block,
// each warp processes 4 tokens per iteration, 8 iterations.
// smem: w_ks^T [256][65], w_vs^T [256][65], q^T [64][257]  (padded, conflict-free)
// x and k stay in registers, broadcast across the warp via shfl.
// ---------------------------------------------------------------------------
#define SMEM_MAIN ((2 * 256 * 65 + 64 * 257) * 4)

__global__ void __launch_bounds__(256, 1) k_main(
    const float* __restrict__ x,
    const float* __restrict__ q,
    const float* __restrict__ wks,
    const float* __restrict__ wvs,
    float* __restrict__ hard)
{
    extern __shared__ float sm[];
    float* s_wk = sm;                  // [256][65]  s_wk[d*65+j] = wks[j, d]
    float* s_wv = sm + 256 * 65;       // [256][65]
    float* s_q  = sm + 2 * 256 * 65;   // [64][257]  s_q[j*257+i] = q[i, j]

    const int tid = threadIdx.x;

    // Coalesced gmem read, conflict-free transposed smem write (pad 65: stride%32==1)
    for (int idx = tid; idx < 64 * 256; idx += 256) {
        int j = idx >> 8, d = idx & 255;
        s_wk[d * 65 + j] = wks[idx];
        s_wv[d * 65 + j] = wvs[idx];
    }
    for (int idx = tid; idx < 256 * 64; idx += 256) {
        int i = idx >> 6, j = idx & 63;
        s_q[j * 257 + i] = q[idx];
    }
    __syncthreads();

    const int lane = tid & 31;
    const int w    = tid >> 5;
    const int base = blockIdx.x * 256;

    for (int it = 0; it < 8; it++) {
        const int t0 = base + (it * 8 + w) * 4;

        // Load x for 4 tokens: xr[t][m] = x[t][m*32 + lane] (coalesced 128B)
        float xr[4][8];
        #pragma unroll
        for (int t = 0; t < 4; t++) {
            const float* xp = x + (size_t)(t0 + t) * 256 + lane;
            #pragma unroll
            for (int m = 0; m < 8; m++) xr[t][m] = xp[m * 32];
        }

        // Phase 1: k = x @ wks^T, v = x @ wvs^T   (lane owns cols lane, lane+32)
        float k0[4] = {0,0,0,0}, k1[4] = {0,0,0,0};
        float v0[4] = {0,0,0,0}, v1[4] = {0,0,0,0};
        #pragma unroll
        for (int m = 0; m < 8; m++) {
            #pragma unroll 8
            for (int s = 0; s < 32; s++) {
                const int d = m * 32 + s;
                const float a0 = s_wk[d * 65 + lane];
                const float a1 = s_wk[d * 65 + 32 + lane];
                const float b0 = s_wv[d * 65 + lane];
                const float b1 = s_wv[d * 65 + 32 + lane];
                #pragma unroll
                for (int t = 0; t < 4; t++) {
                    const float xd = __shfl_sync(0xffffffffu, xr[t][m], s);
                    k0[t] = fmaf(xd, a0, k0[t]);
                    k1[t] = fmaf(xd, a1, k1[t]);
                    v0[t] = fmaf(xd, b0, v0[t]);
                    v1[t] = fmaf(xd, b1, v1[t]);
                }
            }
        }

        // Phase 2: attn[i] = sum_j q[i,j] * k[j]  (lane owns i = lane + 32m)
        float a[4][8];
        #pragma unroll
        for (int t = 0; t < 4; t++)
            #pragma unroll
            for (int m = 0; m < 8; m++) a[t][m] = 0.f;

        #pragma unroll
        for (int h = 0; h < 2; h++) {
            #pragma unroll 8
            for (int s = 0; s < 32; s++) {
                const int j = h * 32 + s;
                float qv[8];
                #pragma unroll
                for (int m = 0; m < 8; m++) qv[m] = s_q[j * 257 + m * 32 + lane];
                #pragma unroll
                for (int t = 0; t < 4; t++) {
                    const float kj = __shfl_sync(0xffffffffu, h ? k1[t] : k0[t], s);
                    #pragma unroll
                    for (int m = 0; m < 8; m++) a[t][m] = fmaf(kj, qv[m], a[t][m]);
                }
            }
        }

        // Phase 3 per token: argmax (first-index tie-break), one-hot, scatter v
        #pragma unroll
        for (int t = 0; t < 4; t++) {
            float bv = a[t][0];
            int   bi = lane;
            // ascending-i local scan, strict > keeps lowest index on ties
            #pragma unroll
            for (int m = 1; m < 8; m++) {
                if (a[t][m] > bv) { bv = a[t][m]; bi = m * 32 + lane; }
            }
            // butterfly reduce with (higher value | lower index) rule
            #pragma unroll
            for (int off = 16; off > 0; off >>= 1) {
                const float ov = __shfl_xor_sync(0xffffffffu, bv, off);
                const int   oi = __shfl_xor_sync(0xffffffffu, bi, off);
                if (ov > bv || (ov == bv && oi < bi)) { bv = ov; bi = oi; }
            }

            // one-hot row: 8 coalesced 128B stores
            const size_t hb = (size_t)(t0 + t) * 256;
            #pragma unroll
            for (int m = 0; m < 8; m++) {
                hard[hb + m * 32 + lane] = (m * 32 + lane == bi) ? 1.0f : 0.0f;
            }

            // scatter v into pooled[b, bi, :]
            const int b = (t0 + t) >> 13;   // token / 8192
            float* pp = g_pooled + (size_t)(b * 256 + bi) * 64;
            atomicAdd(pp + lane,      v0[t]);
            atomicAdd(pp + 32 + lane, v1[t]);
        }
    }
}

// ---------------------------------------------------------------------------
// K2: out[b,q,d] = sum_v pooled[b,q,v] * w_fc[d,v]
// grid = 256 blocks, each handles 16 (b,q) rows; w_fc in padded smem.
// ---------------------------------------------------------------------------
#define SMEM_FC ((256 * 65 + 16 * 64) * 4)

__global__ void __launch_bounds__(256, 1) k_fc(
    const float* __restrict__ wfc,
    float* __restrict__ out)
{
    extern __shared__ float sm[];
    float* s_wf = sm;                // [256][65]  s_wf[d*65+v] = wfc[d, v]
    float* s_p  = sm + 256 * 65;     // [16][64]

    const int tid = threadIdx.x;
    for (int idx = tid; idx < 256 * 64; idx += 256) {
        int d = idx >> 6, v = idx & 63;
        s_wf[d * 65 + v] = wfc[idx];
    }
    const int r0 = blockIdx.x * 16;  // global row = b*256 + qslot
    for (int idx = tid; idx < 16 * 64; idx += 256)
        s_p[idx] = g_pooled[(size_t)r0 * 64 + idx];
    __syncthreads();

    const int d = tid;
    #pragma unroll
    for (int r = 0; r < 16; r++) {
        float acc = 0.f;
        #pragma unroll
        for (int v = 0; v < 64; v++)
            acc = fmaf(s_p[r * 64 + v], s_wf[d * 65 + v], acc);
        out[(size_t)(r0 + r) * 256 + d] = acc;
    }
}

// ---------------------------------------------------------------------------
// Launch
// ---------------------------------------------------------------------------
extern "C" void kernel_launch(void* const* d_in, const int* in_sizes, int n_in,
                              void* d_out, int out_size)
{
    const float* x   = (const float*)d_in[0];
    const float* q   = (const float*)d_in[1];
    const float* wks = (const float*)d_in[2];
    const float* wvs = (const float*)d_in[3];
    const float* wfc = (const float*)d_in[4];

    float* out  = (float*)d_out;            // (16, 256, 256)
    float* hard = out + OUT_ELE;            // (16, 8192, 256)

    // opt-in to >48KB dynamic smem; first call is outside graph capture
    static bool attr_done = false;
    if (!attr_done) {
        cudaFuncSetAttribute(k_main, cudaFuncAttributeMaxDynamicSharedMemorySize, SMEM_MAIN);
        cudaFuncSetAttribute(k_fc,   cudaFuncAttributeMaxDynamicSharedMemorySize, SMEM_FC);
        attr_done = true;
    }

    k_zero<<<256, 256>>>();
    k_main<<<512, 256, SMEM_MAIN>>>(x, q, wks, wvs, hard);
    k_fc<<<256, 256, SMEM_FC>>>(wfc, out);
}

// round 2
// speedup vs baseline: 1.2517x; 1.2517x over previous
#include <cuda_runtime.h>
#include <cstdint>

#define OUT_ELE (16 * 256 * 256)

typedef unsigned long long u64;

// packed-pair helpers (Blackwell f32x2)
#define PACK2(d, lo, hi) \
    asm("mov.b64 %0, {%1, %2};" : "=l"(d) : "r"(__float_as_uint(lo)), "r"(__float_as_uint(hi)))
#define UNPACK2(lo, hi, s) do { unsigned _ulo, _uhi; \
    asm("mov.b64 {%0, %1}, %2;" : "=r"(_ulo), "=r"(_uhi) : "l"(s)); \
    lo = __uint_as_float(_ulo); hi = __uint_as_float(_uhi); } while (0)
#define FMA2(d, a, b, c) \
    asm("fma.rn.f32x2 %0, %1, %2, %3;" : "=l"(d) : "l"(a), "l"(b), "l"(c))

// pooled[b, qslot, v] accumulator
__device__ float g_pooled[16 * 256 * 64];

// ---------------------------------------------------------------------------
__global__ void __launch_bounds__(256) k_zero() {
    int i = blockIdx.x * 256 + threadIdx.x;
    reinterpret_cast<float4*>(g_pooled)[i] = make_float4(0.f, 0.f, 0.f, 0.f);
}

// ---------------------------------------------------------------------------
// K1: fused k/v proj -> attn -> argmax -> one-hot -> scatter-add v
// 256 threads (8 warps), 1024 blocks, 128 tokens/block (2 iters x 8 warps x 8 tok)
// smem (u64 units): wk2 [256][33], wv2 [256][33], q2 [64][130]
//   wk2[d][c] = (wks[c][d], wks[c+32][d])          c = lane
//   q2[j][p*32+l] = (q[p*64+l][j], q[p*64+32+l][j])
// ---------------------------------------------------------------------------
#define WPAD 33
#define QPAD 130
#define SMEM_MAIN ((2 * 256 * WPAD + 64 * QPAD) * 8)

__global__ void __launch_bounds__(256, 1) k_main(
    const float* __restrict__ x,
    const float* __restrict__ q,
    const float* __restrict__ wks,
    const float* __restrict__ wvs,
    float* __restrict__ hard)
{
    extern __shared__ char smraw[];
    u64* s_wk = (u64*)smraw;                 // [256][WPAD]
    u64* s_wv = s_wk + 256 * WPAD;           // [256][WPAD]
    u64* s_q  = s_wv + 256 * WPAD;           // [64][QPAD]
    float* f_wk = (float*)s_wk;
    float* f_wv = (float*)s_wv;
    float* f_q  = (float*)s_q;

    const int tid = threadIdx.x;

    // ---- fills (coalesced gmem; smem conflicts only 2-8 way, one-time) ----
    for (int idx = tid; idx < 64 * 256; idx += 256) {
        int j = idx >> 8, d = idx & 255;
        int c = j & 31, h = j >> 5;
        f_wk[(d * WPAD + c) * 2 + h] = wks[idx];
        f_wv[(d * WPAD + c) * 2 + h] = wvs[idx];
    }
    for (int idx = tid; idx < 256 * 64; idx += 256) {
        int i = idx >> 6, j = idx & 63;
        int p = i >> 6, r = i & 63;
        f_q[(j * QPAD + p * 32 + (r & 31)) * 2 + (r >> 5)] = q[idx];
    }
    __syncthreads();

    const int lane = tid & 31;
    const int w    = tid >> 5;
    const int base = blockIdx.x * 128;

    for (int it = 0; it < 2; it++) {
        const int t0 = base + it * 64 + w * 8;

        // ---- x loads: xf[t][h*4+c] = x[t][h*128 + lane*4 + c] ----
        float xf[8][8];
        #pragma unroll
        for (int t = 0; t < 8; t++) {
            const float4* xp = (const float4*)(x + (size_t)(t0 + t) * 256) + lane;
            float4 a = xp[0];      // h=0
            float4 b = xp[32];     // h=1
            xf[t][0] = a.x; xf[t][1] = a.y; xf[t][2] = a.z; xf[t][3] = a.w;
            xf[t][4] = b.x; xf[t][5] = b.y; xf[t][6] = b.z; xf[t][7] = b.w;
        }

        // ---- phase 1: K[t]=(k[lane],k[lane+32]), V[t] likewise, packed ----
        u64 K[8], V[8];
        #pragma unroll
        for (int t = 0; t < 8; t++) { K[t] = 0ull; V[t] = 0ull; }

        #pragma unroll
        for (int m = 0; m < 8; m++) {
            #pragma unroll 4
            for (int s = 0; s < 32; s++) {
                const int d = m * 32 + s;
                const u64 wk = s_wk[d * WPAD + lane];
                const u64 wv = s_wv[d * WPAD + lane];
                const int src = (m & 3) * 8 + (s >> 2);   // lane holding x[d]
                const int ri  = (m >> 2) * 4 + (s & 3);   // its register slot
                #pragma unroll
                for (int t = 0; t < 8; t++) {
                    const float xd = __shfl_sync(0xffffffffu, xf[t][ri], src);
                    u64 xp2; PACK2(xp2, xd, xd);
                    FMA2(K[t], xp2, wk, K[t]);
                    FMA2(V[t], xp2, wv, V[t]);
                }
            }
        }

        // ---- phase 2: A[t][p] = (attn[p*64+lane], attn[p*64+32+lane]) ----
        float klo[8], khi[8];
        #pragma unroll
        for (int t = 0; t < 8; t++) UNPACK2(klo[t], khi[t], K[t]);

        u64 A[8][4];
        #pragma unroll
        for (int t = 0; t < 8; t++)
            #pragma unroll
            for (int p = 0; p < 4; p++) A[t][p] = 0ull;

        #pragma unroll
        for (int h = 0; h < 2; h++) {
            #pragma unroll 4
            for (int s = 0; s < 32; s++) {
                const int j = h * 32 + s;
                const u64 q0 = s_q[j * QPAD +       lane];
                const u64 q1 = s_q[j * QPAD +  32 + lane];
                const u64 q2 = s_q[j * QPAD +  64 + lane];
                const u64 q3 = s_q[j * QPAD +  96 + lane];
                #pragma unroll
                for (int t = 0; t < 8; t++) {
                    const float kj = __shfl_sync(0xffffffffu, h ? khi[t] : klo[t], s);
                    u64 kp; PACK2(kp, kj, kj);
                    FMA2(A[t][0], kp, q0, A[t][0]);
                    FMA2(A[t][1], kp, q1, A[t][1]);
                    FMA2(A[t][2], kp, q2, A[t][2]);
                    FMA2(A[t][3], kp, q3, A[t][3]);
                }
            }
        }

        // ---- phase 3: argmax (first-index ties), one-hot, scatter ----
        #pragma unroll
        for (int t = 0; t < 8; t++) {
            float ax, ay;
            UNPACK2(ax, ay, A[t][0]);
            float bv = ax; int bi = lane;
            if (ay > bv) { bv = ay; bi = 32 + lane; }
            #pragma unroll
            for (int p = 1; p < 4; p++) {
                UNPACK2(ax, ay, A[t][p]);
                if (ax > bv) { bv = ax; bi = p * 64 + lane; }
                if (ay > bv) { bv = ay; bi = p * 64 + 32 + lane; }
            }
            #pragma unroll
            for (int off = 16; off > 0; off >>= 1) {
                const float ov = __shfl_xor_sync(0xffffffffu, bv, off);
                const int   oi = __shfl_xor_sync(0xffffffffu, bi, off);
                if (ov > bv || (ov == bv && oi < bi)) { bv = ov; bi = oi; }
            }

            // one-hot row: 2 float4 stores per lane (cols lane*8 .. lane*8+7)
            float4* hp = (float4*)(hard + (size_t)(t0 + t) * 256);
            const int c0 = lane * 8;
            float4 o0, o1;
            o0.x = (c0 + 0 == bi) ? 1.f : 0.f;  o0.y = (c0 + 1 == bi) ? 1.f : 0.f;
            o0.z = (c0 + 2 == bi) ? 1.f : 0.f;  o0.w = (c0 + 3 == bi) ? 1.f : 0.f;
            o1.x = (c0 + 4 == bi) ? 1.f : 0.f;  o1.y = (c0 + 5 == bi) ? 1.f : 0.f;
            o1.z = (c0 + 6 == bi) ? 1.f : 0.f;  o1.w = (c0 + 7 == bi) ? 1.f : 0.f;
            hp[lane * 2]     = o0;
            hp[lane * 2 + 1] = o1;

            // scatter v into pooled[b, bi, :]
            const int b = (t0 + t) >> 13;
            float vlo, vhi;
            UNPACK2(vlo, vhi, V[t]);
            float* pp = g_pooled + (size_t)(b * 256 + bi) * 64;
            atomicAdd(pp + lane,      vlo);
            atomicAdd(pp + 32 + lane, vhi);
        }
    }
}

// ---------------------------------------------------------------------------
// K2: out[b,q,d] = sum_v pooled[b,q,v] * w_fc[d,v]
// ---------------------------------------------------------------------------
#define SMEM_FC ((256 * 65 + 16 * 64) * 4)

__global__ void __launch_bounds__(256, 1) k_fc(
    const float* __restrict__ wfc,
    float* __restrict__ out)
{
    extern __shared__ float sm[];
    float* s_wf = sm;                // [256][65]
    float* s_p  = sm + 256 * 65;     // [16][64]

    const int tid = threadIdx.x;
    for (int idx = tid; idx < 256 * 64; idx += 256) {
        int d = idx >> 6, v = idx & 63;
        s_wf[d * 65 + v] = wfc[idx];
    }
    const int r0 = blockIdx.x * 16;
    for (int idx = tid; idx < 16 * 64; idx += 256)
        s_p[idx] = g_pooled[(size_t)r0 * 64 + idx];
    __syncthreads();

    const int d = tid;
    #pragma unroll
    for (int r = 0; r < 16; r++) {
        float acc = 0.f;
        #pragma unroll
        for (int v = 0; v < 64; v++)
            acc = fmaf(s_p[r * 64 + v], s_wf[d * 65 + v], acc);
        out[(size_t)(r0 + r) * 256 + d] = acc;
    }
}

// ---------------------------------------------------------------------------
extern "C" void kernel_launch(void* const* d_in, const int* in_sizes, int n_in,
                              void* d_out, int out_size)
{
    const float* x   = (const float*)d_in[0];
    const float* q   = (const float*)d_in[1];
    const float* wks = (const float*)d_in[2];
    const float* wvs = (const float*)d_in[3];
    const float* wfc = (const float*)d_in[4];

    float* out  = (float*)d_out;
    float* hard = out + OUT_ELE;

    static bool attr_done = false;
    if (!attr_done) {
        cudaFuncSetAttribute(k_main, cudaFuncAttributeMaxDynamicSharedMemorySize, SMEM_MAIN);
        cudaFuncSetAttribute(k_fc,   cudaFuncAttributeMaxDynamicSharedMemorySize, SMEM_FC);
        attr_done = true;
    }

    k_zero<<<256, 256>>>();
    k_main<<<1024, 256, SMEM_MAIN>>>(x, q, wks, wvs, hard);
    k_fc<<<256, 256, SMEM_FC>>>(wfc, out);
}

// round 3
// speedup vs baseline: 1.5685x; 1.2531x over previous
#include <cuda_runtime.h>
#include <cstdint>

#define OUT_ELE (16 * 256 * 256)

typedef unsigned long long u64;

#define PACK2(d, lo, hi) \
    asm("mov.b64 %0, {%1, %2};" : "=l"(d) : "r"(__float_as_uint(lo)), "r"(__float_as_uint(hi)))
#define UNPACK2(lo, hi, s) do { unsigned _ulo, _uhi; \
    asm("mov.b64 {%0, %1}, %2;" : "=r"(_ulo), "=r"(_uhi) : "l"(s)); \
    lo = __uint_as_float(_ulo); hi = __uint_as_float(_uhi); } while (0)
#define FMA2(d, a, b, c) \
    asm("fma.rn.f32x2 %0, %1, %2, %3;" : "=l"(d) : "l"(a), "l"(b), "l"(c))

// scratch
__device__ float g_pooled[16 * 256 * 64];           // 1 MB
__device__ float g_kv[131072 * 128];                // 64 MB: cols 0-63 = k, 64-127 = v

// ---------------------------------------------------------------------------
__global__ void __launch_bounds__(256) k_zero() {
    int i = blockIdx.x * 256 + threadIdx.x;
    reinterpret_cast<float4*>(g_pooled)[i] = make_float4(0.f, 0.f, 0.f, 0.f);
}

// ---------------------------------------------------------------------------
// K1: kv projection GEMM.  1024 blocks x 256 thr; block = 128 tokens x 128 cols.
// Warp = 16 tokens (8 token-pairs) x 128 cols; lane owns cols lane*4..+3.
// smem per d-chunk(64): sp = packed x token-pairs [64][66] u64 (f32 stride 132)
//                       sw = weights [64 d][132] f32 (cols 0-127 used)
// Per d-step: 8 broadcast LDS.64 (x-pairs) + 1 LDS.128 (w) + 4 movs + 32 FMA2.
// ---------------------------------------------------------------------------
#define SP_F  (64 * 132)            // f32 view of sp
#define SMEM_PROJ ((SP_F + 64 * 132) * 4)

__global__ void __launch_bounds__(256, 2) k_proj(
    const float* __restrict__ x,
    const float* __restrict__ wks,
    const float* __restrict__ wvs)
{
    extern __shared__ float sm[];
    float* sp_f = sm;                 // [64][132] f32 == [64][66] u64
    float* sw   = sm + SP_F;          // [64][132]
    u64*   sp64 = (u64*)sp_f;

    const int tid  = threadIdx.x;
    const int lane = tid & 31;
    const int w    = tid >> 5;
    const int tbase = blockIdx.x * 128;

    u64 acc[8][4];
    #pragma unroll
    for (int tp = 0; tp < 8; tp++)
        #pragma unroll
        for (int c = 0; c < 4; c++) acc[tp][c] = 0ull;

    for (int chunk = 0; chunk < 4; chunk++) {
        const int d0 = chunk * 64;

        // fill sw: warp w loads weight rows c = w*16 .. w*16+15
        #pragma unroll
        for (int rr = 0; rr < 16; rr++) {
            const int c = w * 16 + rr;
            const float* wp = (c < 64 ? wks + c * 256 : wvs + (c - 64) * 256) + d0;
            sw[lane * 132 + c]        = wp[lane];
            sw[(32 + lane) * 132 + c] = wp[32 + lane];
        }
        // fill sp: warp w loads x for tokens tl = w*16 .. +15 (pair-packed)
        #pragma unroll
        for (int rr = 0; rr < 16; rr++) {
            const int tl = w * 16 + rr;
            const float* xp = x + (size_t)(tbase + tl) * 256 + d0;
            const int g = tl >> 1, h = tl & 1;
            sp_f[lane * 132 + g * 2 + h]        = xp[lane];
            sp_f[(32 + lane) * 132 + g * 2 + h] = xp[32 + lane];
        }
        __syncthreads();

        #pragma unroll 2
        for (int d = 0; d < 64; d++) {
            u64 xq[8];
            #pragma unroll
            for (int tp = 0; tp < 8; tp++)
                xq[tp] = sp64[d * 66 + w * 8 + tp];          // broadcast
            const float4 w4 = *(const float4*)&sw[d * 132 + lane * 4];
            u64 ws[4];
            PACK2(ws[0], w4.x, w4.x); PACK2(ws[1], w4.y, w4.y);
            PACK2(ws[2], w4.z, w4.z); PACK2(ws[3], w4.w, w4.w);
            #pragma unroll
            for (int tp = 0; tp < 8; tp++) {
                FMA2(acc[tp][0], xq[tp], ws[0], acc[tp][0]);
                FMA2(acc[tp][1], xq[tp], ws[1], acc[tp][1]);
                FMA2(acc[tp][2], xq[tp], ws[2], acc[tp][2]);
                FMA2(acc[tp][3], xq[tp], ws[3], acc[tp][3]);
            }
        }
        __syncthreads();
    }

    // epilogue: kv[t][lane*4 .. +3] via STG.128
    #pragma unroll
    for (int tp = 0; tp < 8; tp++) {
        const size_t t = (size_t)tbase + w * 16 + tp * 2;
        float l0,h0,l1,h1,l2,h2,l3,h3;
        UNPACK2(l0,h0,acc[tp][0]); UNPACK2(l1,h1,acc[tp][1]);
        UNPACK2(l2,h2,acc[tp][2]); UNPACK2(l3,h3,acc[tp][3]);
        *(float4*)&g_kv[t * 128 + lane * 4]       = make_float4(l0,l1,l2,l3);
        *(float4*)&g_kv[(t + 1) * 128 + lane * 4] = make_float4(h0,h1,h2,h3);
    }
}

// ---------------------------------------------------------------------------
// K2: attn + argmax + one-hot + v scatter.  2048 blocks x 256 thr, 64 tokens.
// Warp = 8 tokens; acc A[t][i] = (attn[t][i*32+lane], attn[t][i*32+lane+128]).
// smem: q2p [64 j][130] u64  (q col-pairs), ks [64 j][132] f32 (k scalars).
// Per j-step: 4 LDS.64 (q) + 8 broadcast LDS.32 (k) + 8 movs + 32 FMA2.
// ---------------------------------------------------------------------------
#define Q2P_U64 (64 * 130)
#define SMEM_ATTN ((Q2P_U64 * 2 + 64 * 132) * 4)

__global__ void __launch_bounds__(256, 2) k_attn(
    const float* __restrict__ q,
    float* __restrict__ hard)
{
    extern __shared__ float sm[];
    u64*   q2p = (u64*)sm;             // [64][130]
    float* q2f = sm;                   // f32 view
    float* ks  = sm + Q2P_U64 * 2;     // [64][132]

    const int tid  = threadIdx.x;
    const int lane = tid & 31;
    const int w    = tid >> 5;
    const int tblk = blockIdx.x * 64;

    // fill q2p: q2p[j][rr] = (q[rr][j], q[rr+128][j])
    for (int idx = tid; idx < 256 * 64; idx += 256) {
        const int row = idx >> 6, j = idx & 63;
        const int h = row >> 7, rr = row & 127;
        q2f[(j * 130 + rr) * 2 + h] = q[idx];
    }
    // fill ks: ks[j][tl] = k[tblk+tl][j]
    #pragma unroll
    for (int rr = 0; rr < 8; rr++) {
        const int tl = w * 8 + rr;
        const float* kp = g_kv + (size_t)(tblk + tl) * 128;
        ks[lane * 132 + tl]        = kp[lane];
        ks[(32 + lane) * 132 + tl] = kp[32 + lane];
    }
    __syncthreads();

    u64 A[8][4];
    #pragma unroll
    for (int t = 0; t < 8; t++)
        #pragma unroll
        for (int i = 0; i < 4; i++) A[t][i] = 0ull;

    #pragma unroll 2
    for (int j = 0; j < 64; j++) {
        u64 qv[4];
        #pragma unroll
        for (int i = 0; i < 4; i++)
            qv[i] = q2p[j * 130 + i * 32 + lane];
        #pragma unroll
        for (int t = 0; t < 8; t++) {
            const float kc = ks[j * 132 + w * 8 + t];   // broadcast
            u64 kp2; PACK2(kp2, kc, kc);
            FMA2(A[t][0], kp2, qv[0], A[t][0]);
            FMA2(A[t][1], kp2, qv[1], A[t][1]);
            FMA2(A[t][2], kp2, qv[2], A[t][2]);
            FMA2(A[t][3], kp2, qv[3], A[t][3]);
        }
    }

    // epilogue
    #pragma unroll
    for (int t = 0; t < 8; t++) {
        const int tglob = tblk + w * 8 + t;
        float lo[4], hi[4];
        #pragma unroll
        for (int i = 0; i < 4; i++) UNPACK2(lo[i], hi[i], A[t][i]);

        // ascending-column scan (lo: i*32+lane, then hi: 128+i*32+lane)
        float bv = lo[0]; int bi = lane;
        #pragma unroll
        for (int i = 1; i < 4; i++)
            if (lo[i] > bv) { bv = lo[i]; bi = i * 32 + lane; }
        #pragma unroll
        for (int i = 0; i < 4; i++)
            if (hi[i] > bv) { bv = hi[i]; bi = 128 + i * 32 + lane; }
        #pragma unroll
        for (int off = 16; off > 0; off >>= 1) {
            const float ov = __shfl_xor_sync(0xffffffffu, bv, off);
            const int   oi = __shfl_xor_sync(0xffffffffu, bi, off);
            if (ov > bv || (ov == bv && oi < bi)) { bv = ov; bi = oi; }
        }

        // one-hot row
        float4* hp = (float4*)(hard + (size_t)tglob * 256);
        const int c0 = lane * 8;
        float4 o0, o1;
        o0.x = (c0 + 0 == bi) ? 1.f : 0.f;  o0.y = (c0 + 1 == bi) ? 1.f : 0.f;
        o0.z = (c0 + 2 == bi) ? 1.f : 0.f;  o0.w = (c0 + 3 == bi) ? 1.f : 0.f;
        o1.x = (c0 + 4 == bi) ? 1.f : 0.f;  o1.y = (c0 + 5 == bi) ? 1.f : 0.f;
        o1.z = (c0 + 6 == bi) ? 1.f : 0.f;  o1.w = (c0 + 7 == bi) ? 1.f : 0.f;
        hp[lane * 2]     = o0;
        hp[lane * 2 + 1] = o1;

        // scatter v
        const float* vp = g_kv + (size_t)tglob * 128 + 64;
        const float v0 = vp[lane], v1 = vp[32 + lane];
        const int b = tglob >> 13;
        float* pp = g_pooled + (size_t)(b * 256 + bi) * 64;
        atomicAdd(pp + lane,      v0);
        atomicAdd(pp + 32 + lane, v1);
    }
}

// ---------------------------------------------------------------------------
// K3: out[b,q,d] = sum_v pooled[b,q,v] * w_fc[d,v]
// ---------------------------------------------------------------------------
#define SMEM_FC ((256 * 65 + 16 * 64) * 4)

__global__ void __launch_bounds__(256, 1) k_fc(
    const float* __restrict__ wfc,
    float* __restrict__ out)
{
    extern __shared__ float sm[];
    float* s_wf = sm;
    float* s_p  = sm + 256 * 65;

    const int tid = threadIdx.x;
    for (int idx = tid; idx < 256 * 64; idx += 256) {
        int d = idx >> 6, v = idx & 63;
        s_wf[d * 65 + v] = wfc[idx];
    }
    const int r0 = blockIdx.x * 16;
    for (int idx = tid; idx < 16 * 64; idx += 256)
        s_p[idx] = g_pooled[(size_t)r0 * 64 + idx];
    __syncthreads();

    const int d = tid;
    #pragma unroll
    for (int r = 0; r < 16; r++) {
        float acc = 0.f;
        #pragma unroll
        for (int v = 0; v < 64; v++)
            acc = fmaf(s_p[r * 64 + v], s_wf[d * 65 + v], acc);
        out[(size_t)(r0 + r) * 256 + d] = acc;
    }
}

// ---------------------------------------------------------------------------
extern "C" void kernel_launch(void* const* d_in, const int* in_sizes, int n_in,
                              void* d_out, int out_size)
{
    const float* x   = (const float*)d_in[0];
    const float* q   = (const float*)d_in[1];
    const float* wks = (const float*)d_in[2];
    const float* wvs = (const float*)d_in[3];
    const float* wfc = (const float*)d_in[4];

    float* out  = (float*)d_out;
    float* hard = out + OUT_ELE;

    static bool attr_done = false;
    if (!attr_done) {
        cudaFuncSetAttribute(k_proj, cudaFuncAttributeMaxDynamicSharedMemorySize, SMEM_PROJ);
        cudaFuncSetAttribute(k_attn, cudaFuncAttributeMaxDynamicSharedMemorySize, SMEM_ATTN);
        cudaFuncSetAttribute(k_fc,   cudaFuncAttributeMaxDynamicSharedMemorySize, SMEM_FC);
        attr_done = true;
    }

    k_zero<<<256, 256>>>();
    k_proj<<<1024, 256, SMEM_PROJ>>>(x, wks, wvs);
    k_attn<<<2048, 256, SMEM_ATTN>>>(q, hard);
    k_fc<<<256, 256, SMEM_FC>>>(wfc, out);
}